// round 3
// baseline (speedup 1.0000x reference)
#include <cuda_runtime.h>
#include <cuda_fp16.h>
#include <cstdint>

// ============================================================
// Problem: out[B,256] = relu(X[B,1024] @ W^T + c)
//   X = [text | image], W/c precomputed from small weights.
//   B = 65536, H = 256, K = 1024.
// ============================================================
#define HDIM 256
#define KTOT 1024

// ---------------- device scratch ----------------
__device__ float  g_M1[HDIM * HDIM];
__device__ float  g_G1[HDIM * HDIM];
__device__ float  g_G2[HDIM * HDIM];
__device__ __half g_W16[HDIM * KTOT];   // fused weight, fp16, [256 rows][1024 k]
__device__ float  g_c[HDIM];

// ---------------- PTX helpers ----------------
__device__ __forceinline__ uint32_t smem_u32(const void* p) {
    uint32_t a;
    asm("{ .reg .u64 t; cvta.to.shared.u64 t, %1; cvt.u32.u64 %0, t; }"
        : "=r"(a) : "l"(p));
    return a;
}

#define SW(x) ((x) ^ (((x) >> 3) & 0x70))

#define LDSM_X4(r0, r1, r2, r3, addr) \
    asm volatile("ldmatrix.sync.aligned.m8n8.x4.shared.b16 {%0,%1,%2,%3}, [%4];\n" \
        : "=r"(r0), "=r"(r1), "=r"(r2), "=r"(r3) : "r"(addr))

#define MMA16816(d, a, b0_, b1_) \
    asm volatile("mma.sync.aligned.m16n8k16.row.col.f32.f16.f16.f32 " \
        "{%0,%1,%2,%3}, {%4,%5,%6,%7}, {%8,%9}, {%0,%1,%2,%3};\n" \
        : "+f"((d)[0]), "+f"((d)[1]), "+f"((d)[2]), "+f"((d)[3]) \
        : "r"((a)[0]), "r"((a)[1]), "r"((a)[2]), "r"((a)[3]), "r"(b0_), "r"(b1_))

#define CP_ASYNC16(dst, src) \
    asm volatile("cp.async.cg.shared.global [%0], [%1], 16;\n" :: "r"(dst), "l"(src))
#define CP_COMMIT() asm volatile("cp.async.commit_group;\n")
#define CP_WAIT0()  asm volatile("cp.async.wait_group 0;\n" ::: "memory")

// ============================================================
// Precompute GEMMs: 32x32 tiles, 2x2 per thread, high CTA parallelism
// ============================================================
template<bool HALF_OUT>
__device__ __forceinline__ void gemm32_body(const float* __restrict__ A, int lda,
                                            const float* __restrict__ B, int ldb,
                                            void* __restrict__ C, int ldc, int K,
                                            int i0, int j0) {
    __shared__ float As[32][34];   // transposed: As[k][m]
    __shared__ float Bs[32][34];   // Bs[k][n]
    const int t = threadIdx.x;
    const int tx = t & 15, ty = t >> 4;
    float acc[2][2] = {};

    for (int k0 = 0; k0 < K; k0 += 32) {
        #pragma unroll
        for (int u = 0; u < 4; u++) {
            int idx = t + u * 256;
            int r = idx >> 5, c = idx & 31;
            As[c][r] = A[(size_t)(i0 + r) * lda + k0 + c];
            Bs[r][c] = B[(size_t)(k0 + r) * ldb + j0 + c];
        }
        __syncthreads();
        #pragma unroll
        for (int k = 0; k < 32; k++) {
            float2 a2 = *(const float2*)&As[k][ty * 2];
            float2 b2 = *(const float2*)&Bs[k][tx * 2];
            acc[0][0] += a2.x * b2.x; acc[0][1] += a2.x * b2.y;
            acc[1][0] += a2.y * b2.x; acc[1][1] += a2.y * b2.y;
        }
        __syncthreads();
    }
    #pragma unroll
    for (int r = 0; r < 2; r++)
        #pragma unroll
        for (int c = 0; c < 2; c++) {
            size_t o = (size_t)(i0 + ty * 2 + r) * ldc + j0 + tx * 2 + c;
            if (HALF_OUT) ((__half*)C)[o] = __float2half_rn(acc[r][c]);
            else          ((float*)C)[o]  = acc[r][c];
        }
}

// M1 = Wo @ Wv
__global__ void k_M1(const float* __restrict__ Wo, const float* __restrict__ Wv) {
    gemm32_body<false>(Wo, 256, Wv, 256, g_M1, 256, 256,
                       blockIdx.y * 32, blockIdx.x * 32);
}
// z=0: G1 = Wf1 @ M1 ; z=1: G2 = Wf2 @ M1
__global__ void k_G(const float* __restrict__ W_fuse) {
    const float* A = W_fuse + blockIdx.z * 256;
    float* C = blockIdx.z ? g_G2 : g_G1;
    gemm32_body<false>(A, 512, g_M1, 256, C, 256, 256,
                       blockIdx.y * 32, blockIdx.x * 32);
}
// z=0: W[:, 0:512] = G2 @ W_text ; z=1: W[:, 512:1024] = G1 @ W_img  (fp16 out)
__global__ void k_W(const float* __restrict__ W_text, const float* __restrict__ W_img) {
    const float* A = blockIdx.z ? g_G1 : g_G2;
    const float* B = blockIdx.z ? W_img : W_text;
    __half* C = g_W16 + blockIdx.z * 512;
    gemm32_body<true>(A, 256, B, 512, C, 1024, 256,
                      blockIdx.y * 32, blockIdx.x * 32);
}

// bias: c = G1*b_img + G2*b_text + (Wf1+Wf2)*b1 + b_fuse ; b1 = Wo*bv + bo
__global__ void p4_kernel(const float* __restrict__ Wo,
                          const float* __restrict__ in_proj_b,
                          const float* __restrict__ out_proj_b,
                          const float* __restrict__ W_fuse,
                          const float* __restrict__ b_text,
                          const float* __restrict__ b_img,
                          const float* __restrict__ b_fuse) {
    __shared__ float b1[HDIM];
    int i = threadIdx.x;
    const float* bv = in_proj_b + 2 * HDIM;
    float a = 0.f;
    #pragma unroll 8
    for (int k = 0; k < HDIM; k++) a += Wo[i * HDIM + k] * bv[k];
    b1[i] = a + out_proj_b[i];
    __syncthreads();
    float acc = b_fuse[i];
    #pragma unroll 4
    for (int k = 0; k < HDIM; k++) {
        acc += g_G1[i * HDIM + k] * b_img[k]
             + g_G2[i * HDIM + k] * b_text[k]
             + (W_fuse[i * 512 + k] + W_fuse[i * 512 + 256 + k]) * b1[k];
    }
    g_c[i] = acc;
}

// ============================================================
// Main GEMM: CTA 128x256, 8 warps of 64x64, K-chunk 64,
// double-buffered, fp16 single-pass mma.sync, cp.async for B
// ============================================================
#define STAGE 49152                    // 16KB A + 32KB B
#define DYNSMEM (1024 + 1024 + 2 * STAGE)   // align slack + bias + 2 stages

__global__ void __launch_bounds__(256)
fused_gemm(const float* __restrict__ text, const float* __restrict__ image,
           float* __restrict__ out) {
    extern __shared__ char smem_raw[];
    char* dsm = (char*)(((uintptr_t)smem_raw + 1023) & ~(uintptr_t)1023);
    const uint32_t sb = smem_u32(dsm);
    const int tid = threadIdx.x;
    const int lane = tid & 31;
    const int wid = tid >> 5;
    const int wm = wid & 1;            // 2 m-blocks of 64
    const int wn = wid >> 1;           // 4 n-blocks of 64
    const int mblk = blockIdx.x;

    float* bias_s = (float*)dsm;
    bias_s[tid] = g_c[tid];

    const float* srcT = text  + (size_t)mblk * 128 * 512;
    const float* srcI = image + (size_t)mblk * 128 * 512;

    const int a_c4 = tid & 15, a_r0 = tid >> 4;   // A tile: r = a_r0 + u*16
    const int b_c16 = tid & 7, b_r0 = tid >> 3;   // B tile: r = b_r0 + u*32

    // -------- prologue: chunk 0 --------
    float4 fa[8];
    #pragma unroll
    for (int u = 0; u < 8; u++)
        fa[u] = __ldg((const float4*)(srcT + (size_t)(a_r0 + u * 16) * 512 + a_c4 * 4));
    {
        uint32_t Bb = sb + 1024 + 16384;
        #pragma unroll
        for (int u = 0; u < 8; u++) {
            int r = b_r0 + u * 32;
            uint32_t dst = Bb + SW((uint32_t)(r * 128 + b_c16 * 16));
            CP_ASYNC16(dst, g_W16 + (size_t)r * 1024 + b_c16 * 8);
        }
        CP_COMMIT();
    }
    {
        char* Ab = dsm + 1024;
        #pragma unroll
        for (int u = 0; u < 8; u++) {
            int r = a_r0 + u * 16;
            uint32_t off = SW((uint32_t)(r * 128 + a_c4 * 8));
            __half2 h0 = __floats2half2_rn(fa[u].x, fa[u].y);
            __half2 h1 = __floats2half2_rn(fa[u].z, fa[u].w);
            *(uint2*)(Ab + off) = make_uint2(*(uint32_t*)&h0, *(uint32_t*)&h1);
        }
    }
    CP_WAIT0();
    __syncthreads();

    float acc[4][8][4] = {};

    const uint32_t xorv  = (uint32_t)((lane & 7) << 4);
    const int      rl    = lane & 15;
    const uint32_t khalf = (uint32_t)(((lane >> 4) & 1) * 16);

    #pragma unroll 1
    for (int kc = 0; kc < 16; kc++) {
        const int cur = kc & 1;
        const int nxt = cur ^ 1;

        if (kc < 15) {
            const int kn = kc + 1;
            const float* src = (kn < 8) ? srcT : srcI;
            const int kl = (kn & 7) * 64;
            #pragma unroll
            for (int u = 0; u < 8; u++)
                fa[u] = __ldg((const float4*)(src + (size_t)(a_r0 + u * 16) * 512 + kl + a_c4 * 4));
            uint32_t Bb = sb + 1024 + nxt * STAGE + 16384;
            #pragma unroll
            for (int u = 0; u < 8; u++) {
                int r = b_r0 + u * 32;
                uint32_t dst = Bb + SW((uint32_t)(r * 128 + b_c16 * 16));
                CP_ASYNC16(dst, g_W16 + (size_t)r * 1024 + kn * 64 + b_c16 * 8);
            }
            CP_COMMIT();
        }

        // -------- compute on cur --------
        const uint32_t Ab = sb + 1024 + cur * STAGE;
        const uint32_t Bb = Ab + 16384;
        #pragma unroll
        for (int ks = 0; ks < 4; ks++) {
            uint32_t a[4][4];
            #pragma unroll
            for (int im = 0; im < 4; im++) {
                uint32_t addr = (Ab + (uint32_t)((wm * 64 + im * 16 + rl) * 128)
                                    + (uint32_t)(ks * 32) + khalf) ^ xorv;
                LDSM_X4(a[im][0], a[im][1], a[im][2], a[im][3], addr);
            }
            #pragma unroll
            for (int in_ = 0; in_ < 4; in_++) {
                uint32_t b0, b1, b2, b3;
                uint32_t addr = (Bb + (uint32_t)((wn * 64 + in_ * 16 + rl) * 128)
                                    + (uint32_t)(ks * 32) + khalf) ^ xorv;
                LDSM_X4(b0, b1, b2, b3, addr);
                #pragma unroll
                for (int im = 0; im < 4; im++) {
                    MMA16816(acc[im][2 * in_],     a[im], b0, b2);
                    MMA16816(acc[im][2 * in_ + 1], a[im], b1, b3);
                }
            }
        }

        if (kc < 15) {
            char* Abn = dsm + 1024 + nxt * STAGE;
            #pragma unroll
            for (int u = 0; u < 8; u++) {
                int r = a_r0 + u * 16;
                uint32_t off = SW((uint32_t)(r * 128 + a_c4 * 8));
                __half2 h0 = __floats2half2_rn(fa[u].x, fa[u].y);
                __half2 h1 = __floats2half2_rn(fa[u].z, fa[u].w);
                *(uint2*)(Abn + off) = make_uint2(*(uint32_t*)&h0, *(uint32_t*)&h1);
            }
            CP_WAIT0();
        }
        __syncthreads();
    }

    // -------- epilogue: + bias, relu, store --------
    const int g = lane >> 2;
    const int cpair = (lane & 3) * 2;
    #pragma unroll
    for (int im = 0; im < 4; im++) {
        int m0 = mblk * 128 + wm * 64 + im * 16 + g;
        #pragma unroll
        for (int j = 0; j < 8; j++) {
            int n = wn * 64 + j * 8 + cpair;
            float bv0 = bias_s[n], bv1 = bias_s[n + 1];
            float2 v0 = make_float2(fmaxf(acc[im][j][0] + bv0, 0.f),
                                    fmaxf(acc[im][j][1] + bv1, 0.f));
            float2 v1 = make_float2(fmaxf(acc[im][j][2] + bv0, 0.f),
                                    fmaxf(acc[im][j][3] + bv1, 0.f));
            *(float2*)(out + (size_t)m0 * 256 + n)       = v0;
            *(float2*)(out + (size_t)(m0 + 8) * 256 + n) = v1;
        }
    }
}

// ============================================================
// kernel_launch
// ============================================================
extern "C" void kernel_launch(void* const* d_in, const int* in_sizes, int n_in,
                              void* d_out, int out_size) {
    const float* text       = (const float*)d_in[0];
    const float* image      = (const float*)d_in[1];
    const float* W_text     = (const float*)d_in[2];
    const float* b_text     = (const float*)d_in[3];
    const float* W_img      = (const float*)d_in[4];
    const float* b_img      = (const float*)d_in[5];
    const float* in_proj_w  = (const float*)d_in[6];
    const float* in_proj_b  = (const float*)d_in[7];
    const float* out_proj_w = (const float*)d_in[8];
    const float* out_proj_b = (const float*)d_in[9];
    const float* W_fuse     = (const float*)d_in[10];
    const float* b_fuse     = (const float*)d_in[11];
    const int batch = in_sizes[0] / 512;

    // Precompute chain (4 launches):
    //   M1 = Wo @ Wv ; G1/G2 = Wf1/Wf2 @ M1 ; W = [G2@W_text | G1@W_img] (fp16) ; bias
    k_M1<<<dim3(8, 8), 256>>>(out_proj_w, in_proj_w + 512 * 256);
    k_G <<<dim3(8, 8, 2), 256>>>(W_fuse);
    k_W <<<dim3(16, 8, 2), 256>>>(W_text, W_img);
    p4_kernel<<<1, 256>>>(out_proj_w, in_proj_b, out_proj_b, W_fuse,
                          b_text, b_img, b_fuse);

    cudaFuncSetAttribute(fused_gemm, cudaFuncAttributeMaxDynamicSharedMemorySize, DYNSMEM);
    fused_gemm<<<batch / 128, 256, DYNSMEM>>>(text, image, (float*)d_out);
}

// round 4
// speedup vs baseline: 1.9346x; 1.9346x over previous
#include <cuda_runtime.h>
#include <cuda_fp16.h>
#include <cstdint>

// ============================================================
// Problem: out[B,256] = relu(X[B,1024] @ W^T + c)
//   X = [text | image], W/c precomputed from small weights.
//   B = 65536, H = 256, K = 1024.
// ============================================================
#define HDIM 256
#define KTOT 1024

// ---------------- device scratch ----------------
__device__ float  g_M1[HDIM * HDIM];
__device__ float  g_G1[HDIM * HDIM];
__device__ float  g_G2[HDIM * HDIM];
__device__ __half g_W16[HDIM * KTOT];   // fused weight, fp16, [256 rows][1024 k]
__device__ float  g_b1[HDIM];
__device__ float  g_c[HDIM];

// ---------------- PTX helpers ----------------
__device__ __forceinline__ uint32_t smem_u32(const void* p) {
    uint32_t a;
    asm("{ .reg .u64 t; cvta.to.shared.u64 t, %1; cvt.u32.u64 %0, t; }"
        : "=r"(a) : "l"(p));
    return a;
}

#define SW(x) ((x) ^ (((x) >> 3) & 0x70))

#define LDSM_X4(r0, r1, r2, r3, addr) \
    asm volatile("ldmatrix.sync.aligned.m8n8.x4.shared.b16 {%0,%1,%2,%3}, [%4];\n" \
        : "=r"(r0), "=r"(r1), "=r"(r2), "=r"(r3) : "r"(addr))

#define MMA16816(d, a, b0_, b1_) \
    asm volatile("mma.sync.aligned.m16n8k16.row.col.f32.f16.f16.f32 " \
        "{%0,%1,%2,%3}, {%4,%5,%6,%7}, {%8,%9}, {%0,%1,%2,%3};\n" \
        : "+f"((d)[0]), "+f"((d)[1]), "+f"((d)[2]), "+f"((d)[3]) \
        : "r"((a)[0]), "r"((a)[1]), "r"((a)[2]), "r"((a)[3]), "r"(b0_), "r"(b1_))

#define CP_ASYNC16(dst, src) \
    asm volatile("cp.async.cg.shared.global [%0], [%1], 16;\n" :: "r"(dst), "l"(src))
#define CP_COMMIT() asm volatile("cp.async.commit_group;\n")
#define CP_WAIT0()  asm volatile("cp.async.wait_group 0;\n" ::: "memory")

// ============================================================
// Precompute GEMMs: 32x32 tiles, 2x2 per thread, high CTA parallelism
// ============================================================
template<bool HALF_OUT>
__device__ __forceinline__ void gemm32_body(const float* __restrict__ A, int lda,
                                            const float* __restrict__ B, int ldb,
                                            void* __restrict__ C, int ldc, int K,
                                            int i0, int j0) {
    __shared__ float As[32][34];   // transposed: As[k][m]
    __shared__ float Bs[32][34];   // Bs[k][n]
    const int t = threadIdx.x;
    const int tx = t & 15, ty = t >> 4;
    float acc[2][2] = {};

    for (int k0 = 0; k0 < K; k0 += 32) {
        #pragma unroll
        for (int u = 0; u < 4; u++) {
            int idx = t + u * 256;
            int r = idx >> 5, c = idx & 31;
            As[c][r] = A[(size_t)(i0 + r) * lda + k0 + c];
            Bs[r][c] = B[(size_t)(k0 + r) * ldb + j0 + c];
        }
        __syncthreads();
        #pragma unroll
        for (int k = 0; k < 32; k++) {
            float2 a2 = *(const float2*)&As[k][ty * 2];
            float2 b2 = *(const float2*)&Bs[k][tx * 2];
            acc[0][0] += a2.x * b2.x; acc[0][1] += a2.x * b2.y;
            acc[1][0] += a2.y * b2.x; acc[1][1] += a2.y * b2.y;
        }
        __syncthreads();
    }
    #pragma unroll
    for (int r = 0; r < 2; r++)
        #pragma unroll
        for (int c = 0; c < 2; c++) {
            size_t o = (size_t)(i0 + ty * 2 + r) * ldc + j0 + tx * 2 + c;
            if (HALF_OUT) ((__half*)C)[o] = __float2half_rn(acc[r][c]);
            else          ((float*)C)[o]  = acc[r][c];
        }
}

// M1 = Wo @ Wv
__global__ void k_M1(const float* __restrict__ Wo, const float* __restrict__ Wv) {
    gemm32_body<false>(Wo, 256, Wv, 256, g_M1, 256, 256,
                       blockIdx.y * 32, blockIdx.x * 32);
}
// z=0: G1 = Wf1 @ M1 ; z=1: G2 = Wf2 @ M1
__global__ void k_G(const float* __restrict__ W_fuse) {
    const float* A = W_fuse + blockIdx.z * 256;
    float* C = blockIdx.z ? g_G2 : g_G1;
    gemm32_body<false>(A, 512, g_M1, 256, C, 256, 256,
                       blockIdx.y * 32, blockIdx.x * 32);
}
// z=0: W[:, 0:512] = G2 @ W_text ; z=1: W[:, 512:1024] = G1 @ W_img  (fp16 out)
__global__ void k_W(const float* __restrict__ W_text, const float* __restrict__ W_img) {
    const float* A = blockIdx.z ? g_G1 : g_G2;
    const float* B = blockIdx.z ? W_img : W_text;
    __half* C = g_W16 + blockIdx.z * 512;
    gemm32_body<true>(A, 256, B, 512, C, 1024, 256,
                      blockIdx.y * 32, blockIdx.x * 32);
}

// ============================================================
// Bias precompute, parallelized:
//   b1 = Wo @ bv + bo                      (256 CTAs, tree reduce)
//   c  = G1@b_img + G2@b_text + (Wf1+Wf2)@b1 + b_fuse
// ============================================================
__global__ void k_b1(const float* __restrict__ Wo,
                     const float* __restrict__ in_proj_b,
                     const float* __restrict__ out_proj_b) {
    __shared__ float red[8];
    const int i = blockIdx.x, k = threadIdx.x;
    float v = Wo[i * HDIM + k] * in_proj_b[2 * HDIM + k];
    #pragma unroll
    for (int o = 16; o; o >>= 1) v += __shfl_down_sync(0xffffffffu, v, o);
    if ((k & 31) == 0) red[k >> 5] = v;
    __syncthreads();
    if (k < 8) {
        float s = red[k];
        #pragma unroll
        for (int o = 4; o; o >>= 1) s += __shfl_down_sync(0xffu, s, o);
        if (k == 0) g_b1[i] = s + out_proj_b[i];
    }
}

__global__ void k_bias(const float* __restrict__ W_fuse,
                       const float* __restrict__ b_text,
                       const float* __restrict__ b_img,
                       const float* __restrict__ b_fuse) {
    __shared__ float red[8];
    const int i = blockIdx.x, k = threadIdx.x;
    float v = g_G1[i * HDIM + k] * b_img[k]
            + g_G2[i * HDIM + k] * b_text[k]
            + (W_fuse[i * 512 + k] + W_fuse[i * 512 + 256 + k]) * g_b1[k];
    #pragma unroll
    for (int o = 16; o; o >>= 1) v += __shfl_down_sync(0xffffffffu, v, o);
    if ((k & 31) == 0) red[k >> 5] = v;
    __syncthreads();
    if (k < 8) {
        float s = red[k];
        #pragma unroll
        for (int o = 4; o; o >>= 1) s += __shfl_down_sync(0xffu, s, o);
        if (k == 0) g_c[i] = s + b_fuse[i];
    }
}

// ============================================================
// Main GEMM: CTA 128x256, 8 warps of 64x64, K-chunk 64,
// double-buffered, fp16 single-pass mma.sync, cp.async for B
// ============================================================
#define STAGE 49152                    // 16KB A + 32KB B
#define DYNSMEM (1024 + 1024 + 2 * STAGE)   // align slack + bias + 2 stages

__global__ void __launch_bounds__(256)
fused_gemm(const float* __restrict__ text, const float* __restrict__ image,
           float* __restrict__ out) {
    extern __shared__ char smem_raw[];
    char* dsm = (char*)(((uintptr_t)smem_raw + 1023) & ~(uintptr_t)1023);
    const uint32_t sb = smem_u32(dsm);
    const int tid = threadIdx.x;
    const int lane = tid & 31;
    const int wid = tid >> 5;
    const int wm = wid & 1;            // 2 m-blocks of 64
    const int wn = wid >> 1;           // 4 n-blocks of 64
    const int mblk = blockIdx.x;

    float* bias_s = (float*)dsm;
    bias_s[tid] = g_c[tid];

    const float* srcT = text  + (size_t)mblk * 128 * 512;
    const float* srcI = image + (size_t)mblk * 128 * 512;

    const int a_c4 = tid & 15, a_r0 = tid >> 4;   // A tile: r = a_r0 + u*16
    const int b_c16 = tid & 7, b_r0 = tid >> 3;   // B tile: r = b_r0 + u*32

    // -------- prologue: chunk 0 --------
    float4 fa[8];
    #pragma unroll
    for (int u = 0; u < 8; u++)
        fa[u] = __ldg((const float4*)(srcT + (size_t)(a_r0 + u * 16) * 512 + a_c4 * 4));
    {
        uint32_t Bb = sb + 1024 + 16384;
        #pragma unroll
        for (int u = 0; u < 8; u++) {
            int r = b_r0 + u * 32;
            uint32_t dst = Bb + SW((uint32_t)(r * 128 + b_c16 * 16));
            CP_ASYNC16(dst, g_W16 + (size_t)r * 1024 + b_c16 * 8);
        }
        CP_COMMIT();
    }
    {
        char* Ab = dsm + 1024;
        #pragma unroll
        for (int u = 0; u < 8; u++) {
            int r = a_r0 + u * 16;
            uint32_t off = SW((uint32_t)(r * 128 + a_c4 * 8));
            __half2 h0 = __floats2half2_rn(fa[u].x, fa[u].y);
            __half2 h1 = __floats2half2_rn(fa[u].z, fa[u].w);
            *(uint2*)(Ab + off) = make_uint2(*(uint32_t*)&h0, *(uint32_t*)&h1);
        }
    }
    CP_WAIT0();
    __syncthreads();

    float acc[4][8][4] = {};

    const uint32_t xorv  = (uint32_t)((lane & 7) << 4);
    const int      rl    = lane & 15;
    const uint32_t khalf = (uint32_t)(((lane >> 4) & 1) * 16);

    #pragma unroll 1
    for (int kc = 0; kc < 16; kc++) {
        const int cur = kc & 1;
        const int nxt = cur ^ 1;

        if (kc < 15) {
            const int kn = kc + 1;
            const float* src = (kn < 8) ? srcT : srcI;
            const int kl = (kn & 7) * 64;
            #pragma unroll
            for (int u = 0; u < 8; u++)
                fa[u] = __ldg((const float4*)(src + (size_t)(a_r0 + u * 16) * 512 + kl + a_c4 * 4));
            uint32_t Bb = sb + 1024 + nxt * STAGE + 16384;
            #pragma unroll
            for (int u = 0; u < 8; u++) {
                int r = b_r0 + u * 32;
                uint32_t dst = Bb + SW((uint32_t)(r * 128 + b_c16 * 16));
                CP_ASYNC16(dst, g_W16 + (size_t)r * 1024 + kn * 64 + b_c16 * 8);
            }
            CP_COMMIT();
        }

        // -------- compute on cur --------
        const uint32_t Ab = sb + 1024 + cur * STAGE;
        const uint32_t Bb = Ab + 16384;
        #pragma unroll
        for (int ks = 0; ks < 4; ks++) {
            uint32_t a[4][4];
            #pragma unroll
            for (int im = 0; im < 4; im++) {
                uint32_t addr = (Ab + (uint32_t)((wm * 64 + im * 16 + rl) * 128)
                                    + (uint32_t)(ks * 32) + khalf) ^ xorv;
                LDSM_X4(a[im][0], a[im][1], a[im][2], a[im][3], addr);
            }
            #pragma unroll
            for (int in_ = 0; in_ < 4; in_++) {
                uint32_t b0, b1, b2, b3;
                uint32_t addr = (Bb + (uint32_t)((wn * 64 + in_ * 16 + rl) * 128)
                                    + (uint32_t)(ks * 32) + khalf) ^ xorv;
                LDSM_X4(b0, b1, b2, b3, addr);
                #pragma unroll
                for (int im = 0; im < 4; im++) {
                    MMA16816(acc[im][2 * in_],     a[im], b0, b2);
                    MMA16816(acc[im][2 * in_ + 1], a[im], b1, b3);
                }
            }
        }

        if (kc < 15) {
            char* Abn = dsm + 1024 + nxt * STAGE;
            #pragma unroll
            for (int u = 0; u < 8; u++) {
                int r = a_r0 + u * 16;
                uint32_t off = SW((uint32_t)(r * 128 + a_c4 * 8));
                __half2 h0 = __floats2half2_rn(fa[u].x, fa[u].y);
                __half2 h1 = __floats2half2_rn(fa[u].z, fa[u].w);
                *(uint2*)(Abn + off) = make_uint2(*(uint32_t*)&h0, *(uint32_t*)&h1);
            }
            CP_WAIT0();
        }
        __syncthreads();
    }

    // -------- epilogue: + bias, relu, store --------
    const int g = lane >> 2;
    const int cpair = (lane & 3) * 2;
    #pragma unroll
    for (int im = 0; im < 4; im++) {
        int m0 = mblk * 128 + wm * 64 + im * 16 + g;
        #pragma unroll
        for (int j = 0; j < 8; j++) {
            int n = wn * 64 + j * 8 + cpair;
            float bv0 = bias_s[n], bv1 = bias_s[n + 1];
            float2 v0 = make_float2(fmaxf(acc[im][j][0] + bv0, 0.f),
                                    fmaxf(acc[im][j][1] + bv1, 0.f));
            float2 v1 = make_float2(fmaxf(acc[im][j][2] + bv0, 0.f),
                                    fmaxf(acc[im][j][3] + bv1, 0.f));
            *(float2*)(out + (size_t)m0 * 256 + n)       = v0;
            *(float2*)(out + (size_t)(m0 + 8) * 256 + n) = v1;
        }
    }
}

// ============================================================
// kernel_launch
// ============================================================
extern "C" void kernel_launch(void* const* d_in, const int* in_sizes, int n_in,
                              void* d_out, int out_size) {
    const float* text       = (const float*)d_in[0];
    const float* image      = (const float*)d_in[1];
    const float* W_text     = (const float*)d_in[2];
    const float* b_text     = (const float*)d_in[3];
    const float* W_img      = (const float*)d_in[4];
    const float* b_img      = (const float*)d_in[5];
    const float* in_proj_w  = (const float*)d_in[6];
    const float* in_proj_b  = (const float*)d_in[7];
    const float* out_proj_w = (const float*)d_in[8];
    const float* out_proj_b = (const float*)d_in[9];
    const float* W_fuse     = (const float*)d_in[10];
    const float* b_fuse     = (const float*)d_in[11];
    const int batch = in_sizes[0] / 512;

    // Precompute chain:
    //   M1 = Wo @ Wv ; G1/G2 = Wf1/Wf2 @ M1 ; W = [G2@W_text | G1@W_img] (fp16)
    //   b1 = Wo@bv + bo ; c = G1@b_img + G2@b_text + (Wf1+Wf2)@b1 + b_fuse
    k_M1<<<dim3(8, 8), 256>>>(out_proj_w, in_proj_w + 512 * 256);
    k_b1<<<256, 256>>>(out_proj_w, in_proj_b, out_proj_b);
    k_G <<<dim3(8, 8, 2), 256>>>(W_fuse);
    k_W <<<dim3(16, 8, 2), 256>>>(W_text, W_img);
    k_bias<<<256, 256>>>(W_fuse, b_text, b_img, b_fuse);

    cudaFuncSetAttribute(fused_gemm, cudaFuncAttributeMaxDynamicSharedMemorySize, DYNSMEM);
    fused_gemm<<<batch / 128, 256, DYNSMEM>>>(text, image, (float*)d_out);
}